// round 6
// baseline (speedup 1.0000x reference)
#include <cuda_runtime.h>
#include <math.h>

#define NUM_STEPS 30
#define NBUCKET_MAX 32768     // B * ceil(D/8)^3 must fit (2*24^3 = 27648)
#define CAP 16                // slots per bucket
#define CAP_SHIFT 4
#define OVF_CAP 65536

typedef unsigned long long ull;

// ---- static device scratch (no allocation allowed) ----
__device__ float  g_inv_affine[64 * 16];
__device__ int    g_bcnt[NBUCKET_MAX];
__device__ int    g_ovf_cnt;
__device__ float4 g_slots[NBUCKET_MAX * CAP];   // (px,py,pz, orig idx)
__device__ float4 g_ovf[OVF_CAP];

// ---------------------------------------------------------------------------
// packed f32x2 helpers (sm_103a)
// ---------------------------------------------------------------------------
__device__ __forceinline__ ull pack2(float lo, float hi) {
    ull r; asm("mov.b64 %0, {%1, %2};" : "=l"(r) : "f"(lo), "f"(hi)); return r;
}
__device__ __forceinline__ void unpack2(ull v, float& lo, float& hi) {
    asm("mov.b64 {%0, %1}, %2;" : "=f"(lo), "=f"(hi) : "l"(v));
}
__device__ __forceinline__ ull mul2(ull a, ull b) {
    ull r; asm("mul.rn.f32x2 %0, %1, %2;" : "=l"(r) : "l"(a), "l"(b)); return r;
}
__device__ __forceinline__ ull fma2(ull a, ull b, ull c) {
    ull r; asm("fma.rn.f32x2 %0, %1, %2, %3;" : "=l"(r) : "l"(a), "l"(b), "l"(c)); return r;
}
__device__ __forceinline__ ull lerp2(ull a, ull b, ull t, ull omt) {
    return fma2(b, t, mul2(a, omt));
}

// ---------------------------------------------------------------------------
// init: zero bucket counters + compute affine inverses
// ---------------------------------------------------------------------------
__global__ void init_kernel(const float* __restrict__ affine, int B, int nbucket) {
    int gid = blockIdx.x * blockDim.x + threadIdx.x;
    if (gid < nbucket) g_bcnt[gid] = 0;
    if (gid == 0) g_ovf_cnt = 0;

    if (blockIdx.x == 0 && threadIdx.x < (unsigned)B) {
        int b = threadIdx.x;
        double m[4][8];
        #pragma unroll
        for (int i = 0; i < 4; i++) {
            #pragma unroll
            for (int j = 0; j < 4; j++) m[i][j] = (double)affine[b * 16 + i * 4 + j];
            #pragma unroll
            for (int j = 0; j < 4; j++) m[i][4 + j] = (i == j) ? 1.0 : 0.0;
        }
        for (int col = 0; col < 4; col++) {
            int piv = col;
            double best = fabs(m[col][col]);
            for (int r = col + 1; r < 4; r++) {
                double v = fabs(m[r][col]);
                if (v > best) { best = v; piv = r; }
            }
            if (piv != col)
                for (int j = 0; j < 8; j++) { double t = m[col][j]; m[col][j] = m[piv][j]; m[piv][j] = t; }
            double inv = 1.0 / m[col][col];
            for (int j = 0; j < 8; j++) m[col][j] *= inv;
            for (int r = 0; r < 4; r++) {
                if (r == col) continue;
                double f = m[r][col];
                for (int j = 0; j < 8; j++) m[r][j] -= f * m[col][j];
            }
        }
        #pragma unroll
        for (int i = 0; i < 4; i++)
            #pragma unroll
            for (int j = 0; j < 4; j++)
                g_inv_affine[b * 16 + i * 4 + j] = (float)m[i][4 + j];
    }
}

// ---------------------------------------------------------------------------
// bin: affine transform + place point into its 8^3-cell bucket
// ---------------------------------------------------------------------------
__global__ void bin_kernel(const float* __restrict__ verts,
                           const float* __restrict__ affine,
                           int B, int N, float dmax, float hmax, float wmax,
                           int ncd, int nch, int ncw) {
    int gid = blockIdx.x * blockDim.x + threadIdx.x;
    long long total = (long long)B * N;
    if (gid >= total) return;
    int b = gid / N, n = gid - b * N;

    const float* A = affine + b * 16;
    size_t vb = ((size_t)b * N + n) * 3;
    float vx = verts[vb + 0], vy = verts[vb + 1], vz = verts[vb + 2];
    float px = A[0] * vx + A[1] * vy + A[2]  * vz + A[3];
    float py = A[4] * vx + A[5] * vy + A[6]  * vz + A[7];
    float pz = A[8] * vx + A[9] * vy + A[10] * vz + A[11];

    float pd = fminf(fmaxf(px, 0.0f), dmax);
    float ph = fminf(fmaxf(py, 0.0f), hmax);
    float pw = fminf(fmaxf(pz, 0.0f), wmax);
    int cd = ((int)pd) >> 3;
    int ch = ((int)ph) >> 3;
    int cw = ((int)pw) >> 3;
    int key = ((b * ncd + cd) * nch + ch) * ncw + cw;

    float4 rec = make_float4(px, py, pz, __int_as_float(gid));
    int pos = atomicAdd(&g_bcnt[key], 1);
    if (pos < CAP) {
        g_slots[(key << CAP_SHIFT) + pos] = rec;
    } else {
        int op = atomicAdd(&g_ovf_cnt, 1);
        if (op < OVF_CAP) g_ovf[op] = rec;
    }
}

// ---------------------------------------------------------------------------
// integration body (shared between binned and plain kernels)
// ---------------------------------------------------------------------------
__device__ __forceinline__ void integrate_and_write(
    float px, float py, float pz, int pt,
    const float* __restrict__ flow, float* __restrict__ out,
    int B, int N, int D, int H, int W)
{
    int b = pt / N;
    int n = pt - b * N;

    const int HW  = H * W;
    const int DHW = D * HW;
    const float* base = flow + (size_t)b * 3 * (size_t)DHW;
    const float scale = 1.0f / (float)NUM_STEPS;
    const float dmax = (float)(D - 1), hmax = (float)(H - 1), wmax = (float)(W - 1);

    float xd = px, xh = py, xw = pz;

    float cfd = 1e30f, cfh = 1e30f, cfw = 1e30f;
    int cell = -1;
    ull  c01[8];
    float c2[8];

    #pragma unroll 1
    for (int s = 0; s < NUM_STEPS; s++) {
        float fd = xd - cfd;
        float fh = xh - cfh;
        float fw = xw - cfw;

        float mn = fminf(fd, fminf(fh, fw));
        float mx = fmaxf(fd, fmaxf(fh, fw));
        if (!(mn >= 0.0f && mx < 1.0f)) {
            float pdc = fminf(fmaxf(xd, 0.0f), dmax);
            float phc = fminf(fmaxf(xh, 0.0f), hmax);
            float pwc = fminf(fmaxf(xw, 0.0f), wmax);
            float fd0 = floorf(pdc), fh0 = floorf(phc), fw0 = floorf(pwc);
            int d0 = (int)fd0, h0 = (int)fh0, w0 = (int)fw0;
            fd = pdc - fd0; fh = phc - fh0; fw = pwc - fw0;
            cfd = fd0; cfh = fh0; cfw = fw0;

            int ncell = (d0 << 20) | (h0 << 10) | w0;
            if (ncell != cell) {
                cell = ncell;
                int d1 = min(d0 + 1, D - 1);
                int h1 = min(h0 + 1, H - 1);
                int w1 = min(w0 + 1, W - 1);
                int rd0 = d0 * HW, rd1 = d1 * HW;
                int rh0 = h0 * W,  rh1 = h1 * W;
                int o[8];
                o[0] = rd0 + rh0 + w0; o[1] = rd0 + rh0 + w1;
                o[2] = rd0 + rh1 + w0; o[3] = rd0 + rh1 + w1;
                o[4] = rd1 + rh0 + w0; o[5] = rd1 + rh0 + w1;
                o[6] = rd1 + rh1 + w0; o[7] = rd1 + rh1 + w1;
                const float* p0 = base;
                const float* p1 = base + DHW;
                const float* p2 = base + 2 * DHW;
                #pragma unroll
                for (int k = 0; k < 8; k++) {
                    float a0 = __ldg(p0 + o[k]);
                    float a1 = __ldg(p1 + o[k]);
                    c2[k]  = __ldg(p2 + o[k]);
                    c01[k] = pack2(a0, a1);
                }
            }
        }

        float omfw = 1.0f - fw, omfh = 1.0f - fh, omfd = 1.0f - fd;
        ull W2  = pack2(fw, fw),   OW2 = pack2(omfw, omfw);
        ull H2  = pack2(fh, fh),   OH2 = pack2(omfh, omfh);
        ull D2  = pack2(fd, fd),   OD2 = pack2(omfd, omfd);

        ull l00 = lerp2(c01[0], c01[1], W2, OW2);
        ull l01 = lerp2(c01[2], c01[3], W2, OW2);
        ull l10 = lerp2(c01[4], c01[5], W2, OW2);
        ull l11 = lerp2(c01[6], c01[7], W2, OW2);
        ull m0  = lerp2(l00, l01, H2, OH2);
        ull m1  = lerp2(l10, l11, H2, OH2);
        ull r01 = lerp2(m0, m1, D2, OD2);
        float s0, s1;
        unpack2(r01, s0, s1);

        float q00 = c2[0] * omfw + c2[1] * fw;
        float q01 = c2[2] * omfw + c2[3] * fw;
        float q10 = c2[4] * omfw + c2[5] * fw;
        float q11 = c2[6] * omfw + c2[7] * fw;
        float q0  = q00 * omfh + q01 * fh;
        float q1  = q10 * omfh + q11 * fh;
        float s2  = q0 * omfd + q1 * fd;

        xd = fmaf(s0, scale, xd);
        xh = fmaf(s1, scale, xh);
        xw = fmaf(s2, scale, xw);
    }

    float fix = xd - px, fiy = xh - py, fiz = xw - pz;

    const float* Inv = g_inv_affine + b * 16;
    float ox = Inv[0] * xd + Inv[1] * xh + Inv[2]  * xw + Inv[3];
    float oy = Inv[4] * xd + Inv[5] * xh + Inv[6]  * xw + Inv[7];
    float oz = Inv[8] * xd + Inv[9] * xh + Inv[10] * xw + Inv[11];

    size_t pb = ((size_t)b * N + n) * 3;
    out[pb + 0] = ox;
    out[pb + 1] = oy;
    out[pb + 2] = oz;

    size_t fb = (size_t)B * N * 3 + ((size_t)b * 3) * (size_t)N + n;
    out[fb + 0 * (size_t)N] = fix;
    out[fb + 1 * (size_t)N] = fiy;
    out[fb + 2 * (size_t)N] = fiz;
}

// ---------------------------------------------------------------------------
// binned deform: threads map to bucket slots (spatially coherent warps)
// ---------------------------------------------------------------------------
__global__ __launch_bounds__(256, 4)
void deform_binned_kernel(const float* __restrict__ flow,
                          float* __restrict__ out,
                          int B, int N, int D, int H, int W, int nslots)
{
    int tid = blockIdx.x * blockDim.x + threadIdx.x;
    float4 P;
    if (tid < nslots) {
        int key  = tid >> CAP_SHIFT;
        int slot = tid & (CAP - 1);
        int cnt = g_bcnt[key];
        if (slot >= min(cnt, CAP)) return;
        P = g_slots[tid];
    } else {
        int oi = tid - nslots;
        int ocnt = min(g_ovf_cnt, OVF_CAP);
        if (oi >= ocnt) return;
        P = g_ovf[oi];
    }
    integrate_and_write(P.x, P.y, P.z, __float_as_int(P.w),
                        flow, out, B, N, D, H, W);
}

// ---------------------------------------------------------------------------
// plain fallback (odd configurations)
// ---------------------------------------------------------------------------
__global__ __launch_bounds__(256, 4)
void deform_plain_kernel(const float* __restrict__ verts,
                         const float* __restrict__ affine,
                         const float* __restrict__ flow,
                         float* __restrict__ out,
                         int B, int N, int D, int H, int W)
{
    int gid = blockIdx.x * blockDim.x + threadIdx.x;
    long long total = (long long)B * N;
    if (gid >= total) return;
    int b = gid / N, n = gid - b * N;

    const float* A = affine + b * 16;
    size_t vbase = ((size_t)b * N + n) * 3;
    float vx = verts[vbase + 0], vy = verts[vbase + 1], vz = verts[vbase + 2];
    float px = A[0] * vx + A[1] * vy + A[2]  * vz + A[3];
    float py = A[4] * vx + A[5] * vy + A[6]  * vz + A[7];
    float pz = A[8] * vx + A[9] * vy + A[10] * vz + A[11];

    integrate_and_write(px, py, pz, gid, flow, out, B, N, D, H, W);
}

extern "C" void kernel_launch(void* const* d_in, const int* in_sizes, int n_in,
                              void* d_out, int out_size) {
    const float* verts  = (const float*)d_in[0];
    const float* affine = (const float*)d_in[1];
    const float* flow   = (const float*)d_in[2];
    float* out = (float*)d_out;

    int B = in_sizes[1] / 16;
    int N = in_sizes[0] / (3 * B);
    long long dhw = (long long)in_sizes[2] / (3LL * B);
    int D = (int)llrint(cbrt((double)dhw));
    int H = D, W = D;
    float dmax = (float)(D - 1), hmax = (float)(H - 1), wmax = (float)(W - 1);

    long long total = (long long)B * N;
    int threads = 256;
    int blocks = (int)((total + threads - 1) / threads);

    int ncd = (D + 7) >> 3, nch = (H + 7) >> 3, ncw = (W + 7) >> 3;
    long long nbucket = (long long)B * ncd * nch * ncw;
    // overflow capacity must comfortably exceed expected spill (<1% of points)
    int use_bins = (nbucket <= NBUCKET_MAX && B <= 64 &&
                    total <= (long long)NBUCKET_MAX * CAP &&
                    D <= 1024 && H <= 1024 && W <= 1024) ? 1 : 0;

    if (use_bins) {
        int nslots = (int)(nbucket << CAP_SHIFT);
        int iblocks = (int)((nbucket + threads - 1) / threads);
        init_kernel<<<iblocks, threads>>>(affine, B, (int)nbucket);
        bin_kernel<<<blocks, threads>>>(verts, affine, B, N, dmax, hmax, wmax,
                                        ncd, nch, ncw);
        long long dtotal = (long long)nslots + OVF_CAP;
        int dblocks = (int)((dtotal + threads - 1) / threads);
        deform_binned_kernel<<<dblocks, threads>>>(flow, out, B, N, D, H, W, nslots);
    } else {
        init_kernel<<<1, 256>>>(affine, B, 0);  // just the inverse
        deform_plain_kernel<<<blocks, threads>>>(verts, affine, flow, out,
                                                 B, N, D, H, W);
    }
}

// round 7
// speedup vs baseline: 1.1934x; 1.1934x over previous
#include <cuda_runtime.h>
#include <math.h>

#define NUM_STEPS 30

typedef unsigned long long ull;

// ---------------------------------------------------------------------------
// packed f32x2 helpers (sm_103a)
// ---------------------------------------------------------------------------
__device__ __forceinline__ ull pack2(float lo, float hi) {
    ull r; asm("mov.b64 %0, {%1, %2};" : "=l"(r) : "f"(lo), "f"(hi)); return r;
}
__device__ __forceinline__ void unpack2(ull v, float& lo, float& hi) {
    asm("mov.b64 {%0, %1}, %2;" : "=f"(lo), "=f"(hi) : "l"(v));
}
__device__ __forceinline__ ull mul2(ull a, ull b) {
    ull r; asm("mul.rn.f32x2 %0, %1, %2;" : "=l"(r) : "l"(a), "l"(b)); return r;
}
__device__ __forceinline__ ull fma2(ull a, ull b, ull c) {
    ull r; asm("fma.rn.f32x2 %0, %1, %2, %3;" : "=l"(r) : "l"(a), "l"(b), "l"(c)); return r;
}
__device__ __forceinline__ ull lerp2(ull a, ull b, ull t, ull omt) {
    return fma2(b, t, mul2(a, omt));
}

// ---------------------------------------------------------------------------
// fp32 Gauss-Jordan 4x4 inverse (well-conditioned input: I + 0.01*noise)
// ---------------------------------------------------------------------------
__device__ void inv4x4_f32(const float* __restrict__ A, float* __restrict__ out) {
    float m[4][8];
    #pragma unroll
    for (int i = 0; i < 4; i++) {
        #pragma unroll
        for (int j = 0; j < 4; j++) m[i][j] = A[i * 4 + j];
        #pragma unroll
        for (int j = 0; j < 4; j++) m[i][4 + j] = (i == j) ? 1.0f : 0.0f;
    }
    #pragma unroll
    for (int col = 0; col < 4; col++) {
        int piv = col;
        float best = fabsf(m[col][col]);
        #pragma unroll
        for (int r = 0; r < 4; r++) {
            if (r > col) {
                float v = fabsf(m[r][col]);
                if (v > best) { best = v; piv = r; }
            }
        }
        if (piv != col) {
            #pragma unroll
            for (int j = 0; j < 8; j++) { float t = m[col][j]; m[col][j] = m[piv][j]; m[piv][j] = t; }
        }
        float inv = 1.0f / m[col][col];
        #pragma unroll
        for (int j = 0; j < 8; j++) m[col][j] *= inv;
        #pragma unroll
        for (int r = 0; r < 4; r++) {
            if (r != col) {
                float f = m[r][col];
                #pragma unroll
                for (int j = 0; j < 8; j++) m[r][j] = fmaf(-f, m[col][j], m[r][j]);
            }
        }
    }
    #pragma unroll
    for (int i = 0; i < 4; i++)
        #pragma unroll
        for (int j = 0; j < 4; j++)
            out[i * 4 + j] = m[i][4 + j];
}

// ---------------------------------------------------------------------------
// single fused kernel
// ---------------------------------------------------------------------------
__global__ __launch_bounds__(256, 4)
void deform_kernel(const float* __restrict__ verts,
                   const float* __restrict__ affine,
                   const float* __restrict__ flow,
                   float* __restrict__ out,
                   int B, int N, int D, int H, int W)
{
    __shared__ float s_inv[2][16];   // a block spans at most 2 batch values

    int gid = blockIdx.x * blockDim.x + threadIdx.x;
    long long total = (long long)B * N;

    // block's batch range (contiguous gid -> at most 2 batches per block)
    long long g0 = (long long)blockIdx.x * blockDim.x;
    long long g1 = min(g0 + blockDim.x - 1, total - 1);
    int bmin = (int)(g0 / N);
    int bmax = (int)(g1 / N);

    if (threadIdx.x == 0) {
        inv4x4_f32(affine + bmin * 16, s_inv[0]);
        if (bmax != bmin) inv4x4_f32(affine + bmax * 16, s_inv[1]);
    }
    __syncthreads();

    if (gid >= total) return;
    int b = gid / N;
    int n = gid - b * N;

    // ---- affine transform ----
    const float* A = affine + b * 16;
    size_t vbase = ((size_t)b * N + n) * 3;
    float vx = verts[vbase + 0];
    float vy = verts[vbase + 1];
    float vz = verts[vbase + 2];

    float px = A[0] * vx + A[1] * vy + A[2]  * vz + A[3];
    float py = A[4] * vx + A[5] * vy + A[6]  * vz + A[7];
    float pz = A[8] * vx + A[9] * vy + A[10] * vz + A[11];

    const int HW  = H * W;
    const int DHW = D * HW;
    const float* base = flow + (size_t)b * 3 * (size_t)DHW;
    const float scale = 1.0f / (float)NUM_STEPS;
    const float dmax = (float)(D - 1), hmax = (float)(H - 1), wmax = (float)(W - 1);

    float xd = px, xh = py, xw = pz;

    float cfd = 1e30f, cfh = 1e30f, cfw = 1e30f;
    int cell = -1;
    ull  c01[8];
    float c2[8];

    #pragma unroll 1
    for (int s = 0; s < NUM_STEPS; s++) {
        float fd = xd - cfd;
        float fh = xh - cfh;
        float fw = xw - cfw;

        float mn = fminf(fd, fminf(fh, fw));
        float mx = fmaxf(fd, fmaxf(fh, fw));
        if (!(mn >= 0.0f && mx < 1.0f)) {
            float pdc = fminf(fmaxf(xd, 0.0f), dmax);
            float phc = fminf(fmaxf(xh, 0.0f), hmax);
            float pwc = fminf(fmaxf(xw, 0.0f), wmax);
            float fd0 = floorf(pdc), fh0 = floorf(phc), fw0 = floorf(pwc);
            int d0 = (int)fd0, h0 = (int)fh0, w0 = (int)fw0;
            fd = pdc - fd0; fh = phc - fh0; fw = pwc - fw0;
            cfd = fd0; cfh = fh0; cfw = fw0;

            int ncell = (d0 << 20) | (h0 << 10) | w0;
            if (ncell != cell) {
                cell = ncell;
                int d1 = min(d0 + 1, D - 1);
                int h1 = min(h0 + 1, H - 1);
                int w1 = min(w0 + 1, W - 1);
                int rd0 = d0 * HW, rd1 = d1 * HW;
                int rh0 = h0 * W,  rh1 = h1 * W;
                int o[8];
                o[0] = rd0 + rh0 + w0; o[1] = rd0 + rh0 + w1;
                o[2] = rd0 + rh1 + w0; o[3] = rd0 + rh1 + w1;
                o[4] = rd1 + rh0 + w0; o[5] = rd1 + rh0 + w1;
                o[6] = rd1 + rh1 + w0; o[7] = rd1 + rh1 + w1;
                const float* p0 = base;
                const float* p1 = base + DHW;
                const float* p2 = base + 2 * DHW;
                #pragma unroll
                for (int k = 0; k < 8; k++) {
                    float a0 = __ldg(p0 + o[k]);
                    float a1 = __ldg(p1 + o[k]);
                    c2[k]  = __ldg(p2 + o[k]);
                    c01[k] = pack2(a0, a1);
                }
            }
        }

        float omfw = 1.0f - fw, omfh = 1.0f - fh, omfd = 1.0f - fd;
        ull W2  = pack2(fw, fw),   OW2 = pack2(omfw, omfw);
        ull H2  = pack2(fh, fh),   OH2 = pack2(omfh, omfh);
        ull D2  = pack2(fd, fd),   OD2 = pack2(omfd, omfd);

        ull l00 = lerp2(c01[0], c01[1], W2, OW2);
        ull l01 = lerp2(c01[2], c01[3], W2, OW2);
        ull l10 = lerp2(c01[4], c01[5], W2, OW2);
        ull l11 = lerp2(c01[6], c01[7], W2, OW2);
        ull m0  = lerp2(l00, l01, H2, OH2);
        ull m1  = lerp2(l10, l11, H2, OH2);
        ull r01 = lerp2(m0, m1, D2, OD2);
        float s0, s1;
        unpack2(r01, s0, s1);

        float q00 = c2[0] * omfw + c2[1] * fw;
        float q01 = c2[2] * omfw + c2[3] * fw;
        float q10 = c2[4] * omfw + c2[5] * fw;
        float q11 = c2[6] * omfw + c2[7] * fw;
        float q0  = q00 * omfh + q01 * fh;
        float q1  = q10 * omfh + q11 * fh;
        float s2  = q0 * omfd + q1 * fd;

        xd = fmaf(s0, scale, xd);
        xh = fmaf(s1, scale, xh);
        xw = fmaf(s2, scale, xw);
    }

    // ---- outputs ----
    float fix = xd - px, fiy = xh - py, fiz = xw - pz;

    const float* Inv = s_inv[b - bmin];
    float ox = Inv[0] * xd + Inv[1] * xh + Inv[2]  * xw + Inv[3];
    float oy = Inv[4] * xd + Inv[5] * xh + Inv[6]  * xw + Inv[7];
    float oz = Inv[8] * xd + Inv[9] * xh + Inv[10] * xw + Inv[11];

    size_t pb = ((size_t)b * N + n) * 3;
    out[pb + 0] = ox;
    out[pb + 1] = oy;
    out[pb + 2] = oz;

    size_t fb = (size_t)B * N * 3 + ((size_t)b * 3) * (size_t)N + n;
    out[fb + 0 * (size_t)N] = fix;
    out[fb + 1 * (size_t)N] = fiy;
    out[fb + 2 * (size_t)N] = fiz;
}

extern "C" void kernel_launch(void* const* d_in, const int* in_sizes, int n_in,
                              void* d_out, int out_size) {
    const float* verts  = (const float*)d_in[0];
    const float* affine = (const float*)d_in[1];
    const float* flow   = (const float*)d_in[2];
    float* out = (float*)d_out;

    int B = in_sizes[1] / 16;
    int N = in_sizes[0] / (3 * B);
    long long dhw = (long long)in_sizes[2] / (3LL * B);
    int D = (int)llrint(cbrt((double)dhw));
    int H = D, W = D;

    long long total = (long long)B * N;
    int threads = 256;
    int blocks = (int)((total + threads - 1) / threads);
    deform_kernel<<<blocks, threads>>>(verts, affine, flow, out, B, N, D, H, W);
}